// round 15
// baseline (speedup 1.0000x reference)
#include <cuda_runtime.h>
#include <cstdint>

#define PAD_ID    100000
#define ITEM_ROWS 100001
#define D   64
#define NB  4096
#define L   200
#define NEGW 0.1f
#define C1  (1.0f - NEGW)

#define NB_G1   296            // item Gram blocks
#define NB_GV   32             // user Gram blocks
#define NB_GRAM (NB_G1 + NB_GV)   // 328
#define NB_POS  1024           // pos-loss blocks
#define B_PER_BLK 4
#define CHUNK   64
#define STRIDE  72             // Gram smem stride
#define GRID_TOTAL (NB_GRAM + NB_POS)   // 1352

// ---- pos-path pipeline geometry ----
#define UPAD    208            // 13*16 rows per user (padded)
#define NGROUP  52             // 4 users * 13 groups of 16 rows
#define PSTRIDE 68             // floats per staged row (68 mod 32 == 4 -> conflict-free)
#define STAGE_F (16 * PSTRIDE) // 1088 floats per stage
#define WARP_BUF (2 * STAGE_F) // 2176 floats per warp

// dynamic smem layout (bytes)
#define POSBUF_BYTES (8 * WARP_BUF * 4)       // 69632
#define SIDX_OFF     POSBUF_BYTES
#define SIDX_BYTES   (4 * UPAD * 4)           // 3328
#define VVEC_OFF     (SIDX_OFF + SIDX_BYTES)  // 72960
#define VVEC_BYTES   (B_PER_BLK * D * 4)      // 1024
#define SMEM_DYN     (VVEC_OFF + VVEC_BYTES)  // 73984

// zero-initialized at module load; last block resets them each run
__device__ float g_g1[D * D];
__device__ float g_gv[D * D];
__device__ float g_pos;
__device__ unsigned int g_done;

__device__ __forceinline__ float tf32r(float x) {
    uint32_t r;
    asm("cvt.rna.tf32.f32 %0, %1;" : "=r"(r) : "f"(x));
    return __uint_as_float(r);
}

__device__ __forceinline__ void mma_tf32(float d[4], uint32_t a0, uint32_t a1,
                                         uint32_t a2, uint32_t a3,
                                         uint32_t b0, uint32_t b1) {
    asm volatile(
        "mma.sync.aligned.m16n8k8.row.col.f32.tf32.tf32.f32 "
        "{%0,%1,%2,%3}, {%4,%5,%6,%7}, {%8,%9}, {%0,%1,%2,%3};\n"
        : "+f"(d[0]), "+f"(d[1]), "+f"(d[2]), "+f"(d[3])
        : "r"(a0), "r"(a1), "r"(a2), "r"(a3), "r"(b0), "r"(b1));
}

__device__ __forceinline__ void cp16(uint32_t dst_smem, const void* src) {
    asm volatile("cp.async.cg.shared.global [%0], [%1], 16;\n"
                 :: "r"(dst_smem), "l"(src));
}

__global__ __launch_bounds__(256) void enmf_kernel(
    const int* __restrict__ uids, const int* __restrict__ pos_iids,
    const float* __restrict__ userW, const float* __restrict__ itemW,
    const float* __restrict__ h, float* __restrict__ out)
{
    extern __shared__ float dynsm[];
    __shared__ float hh[D];
    __shared__ float warpsum[8];
    __shared__ unsigned int s_rank;

    const int tid = threadIdx.x;
    const int bid = blockIdx.x;
    if (tid < D) hh[tid] = h[tid];
    __syncthreads();

    // ---- interleave block types so tensor/mem-bound blocks co-reside ----
    int gram_id = -1, pos_id = -1;
    if (bid < NB_GRAM * 4) {
        if ((bid & 3) == 3) gram_id = bid >> 2;
        else                pos_id  = (bid >> 2) * 3 + (bid & 3);
    } else {
        pos_id = NB_GRAM * 3 + (bid - NB_GRAM * 4);
    }

    const int warp = tid >> 5, lane = tid & 31;
    const int gid  = lane >> 2;       // 0..7
    const int tig  = lane & 3;        // 0..3

    if (gram_id >= 0) {
        // ========= Gram path: tf32 mma, double-buffered fill (unchanged) =========
        const bool is_item   = (gram_id < NB_G1);
        const int rows_total = is_item ? ITEM_ROWS : NB;
        const int nblk       = is_item ? NB_G1 : NB_GV;
        const int gb         = is_item ? gram_id : gram_id - NB_G1;
        const int per        = (rows_total + nblk - 1) / nblk;
        const int r0         = gb * per;
        const int r1         = min(r0 + per, rows_total);

        const bool compute_warp = (warp < 4);
        const int Ibase = warp * 16;

        float dacc[8][4];
        #pragma unroll
        for (int n = 0; n < 8; n++)
            #pragma unroll
            for (int k = 0; k < 4; k++) dacc[n][k] = 0.f;

        const float4* hv4 = (const float4*)hh;
        float* smA = dynsm;   // [2][CHUNK][STRIDE]

        auto fill = [&](int buf, int base, int lo) {
            for (int i = tid - lo; i < CHUNK * 16; i += 256 - lo) {
                if (i < 0) continue;
                int r = base + (i >> 4);
                int c4 = i & 15;
                float4 v = make_float4(0.f, 0.f, 0.f, 0.f);
                if (r < r1) {
                    if (is_item) {
                        v = ((const float4*)itemW)[(size_t)r * 16 + c4];
                    } else {
                        float4 u = ((const float4*)userW)[(size_t)uids[r] * 16 + c4];
                        float4 hx = hv4[c4];
                        v = make_float4(u.x * hx.x, u.y * hx.y, u.z * hx.z, u.w * hx.w);
                    }
                    v.x = tf32r(v.x); v.y = tf32r(v.y);
                    v.z = tf32r(v.z); v.w = tf32r(v.w);
                }
                ((float4*)(smA + buf * (CHUNK * STRIDE) + (i >> 4) * STRIDE))[c4] = v;
            }
        };

        fill(0, r0, 0);
        __syncthreads();

        int buf = 0;
        for (int base = r0; base < r1; base += CHUNK, buf ^= 1) {
            if (!compute_warp) {
                if (base + CHUNK < r1) fill(buf ^ 1, base + CHUNK, 128);
            } else {
                #pragma unroll
                for (int ks = 0; ks < 8; ks++) {
                    const float* r0p = smA + buf * (CHUNK * STRIDE) + (ks * 8 + tig) * STRIDE;
                    const float* r1p = smA + buf * (CHUNK * STRIDE) + (ks * 8 + tig + 4) * STRIDE;
                    uint32_t a0 = __float_as_uint(r0p[Ibase + gid]);
                    uint32_t a1 = __float_as_uint(r0p[Ibase + gid + 8]);
                    uint32_t a2 = __float_as_uint(r1p[Ibase + gid]);
                    uint32_t a3 = __float_as_uint(r1p[Ibase + gid + 8]);
                    #pragma unroll
                    for (int nt = 0; nt < 8; nt++) {
                        uint32_t b0 = __float_as_uint(r0p[nt * 8 + gid]);
                        uint32_t b1 = __float_as_uint(r1p[nt * 8 + gid]);
                        mma_tf32(dacc[nt], a0, a1, a2, a3, b0, b1);
                    }
                }
            }
            __syncthreads();
        }

        if (compute_warp) {
            float* dst = is_item ? g_g1 : g_gv;
            const int row0 = Ibase + gid;
            #pragma unroll
            for (int nt = 0; nt < 8; nt++) {
                int col = nt * 8 + tig * 2;
                atomicAdd(&dst[row0 * D + col],           dacc[nt][0]);
                atomicAdd(&dst[row0 * D + col + 1],       dacc[nt][1]);
                atomicAdd(&dst[(row0 + 8) * D + col],     dacc[nt][2]);
                atomicAdd(&dst[(row0 + 8) * D + col + 1], dacc[nt][3]);
            }
        }
    } else {
        // ===== pos path: cp.async 2-stage pipeline + tf32 mma dot products =====
        const int b0 = pos_id * B_PER_BLK;
        int*   sidx = (int*)((char*)dynsm + SIDX_OFF);
        float* vvec = (float*)((char*)dynsm + VVEC_OFF);

        // user vectors v = u*h
        for (int i = tid; i < B_PER_BLK * D; i += 256) {
            int bl = i >> 6, d = i & 63;
            vvec[i] = userW[(size_t)uids[b0 + bl] * D + d] * hh[d];
        }
        // indices padded to 208 per user
        for (int j = tid; j < 4 * UPAD; j += 256) {
            int u = j / UPAD;
            int p = j - u * UPAD;
            sidx[j] = (p < L) ? pos_iids[(size_t)(b0 + u) * L + p] : PAD_ID;
        }
        __syncthreads();

        // B fragments: column n=gid holds user gid's vector (gid>=4 -> zero)
        uint32_t vb0[8], vb1[8];
        #pragma unroll
        for (int c = 0; c < 8; c++) {
            float x0 = (gid < 4) ? tf32r(vvec[gid * D + c * 8 + tig])     : 0.f;
            float x1 = (gid < 4) ? tf32r(vvec[gid * D + c * 8 + tig + 4]) : 0.f;
            vb0[c] = __float_as_uint(x0);
            vb1[c] = __float_as_uint(x1);
        }

        float* wbuf = dynsm + (size_t)warp * WARP_BUF;
        uint32_t wbase = (uint32_t)__cvta_generic_to_shared(wbuf);
        const int myrow   = lane >> 1;          // 0..15
        const int halfoff = (lane & 1) * 128;   // byte offset within a 256B row
        float acc = 0.f;

        auto stage = [&](int s, int g) {
            int u = g & 3, sub = g >> 2;
            int idx = sidx[u * UPAD + sub * 16 + myrow];
            const char* src = (const char*)(itemW + (size_t)idx * D) + halfoff;
            uint32_t dst = wbase + (uint32_t)(s * STAGE_F + myrow * PSTRIDE) * 4 + halfoff;
            #pragma unroll
            for (int i = 0; i < 8; i++)
                cp16(dst + i * 16, src + i * 16);
            asm volatile("cp.async.commit_group;\n" ::: "memory");
        };

        auto compute = [&](int s, int g) {
            int u = g & 3, sub = g >> 2;
            const float* B = wbuf + s * STAGE_F;
            float dac[4] = {0.f, 0.f, 0.f, 0.f};
            #pragma unroll
            for (int c = 0; c < 8; c++) {
                uint32_t a0 = __float_as_uint(B[gid * PSTRIDE + c * 8 + tig]);
                uint32_t a1 = __float_as_uint(B[(gid + 8) * PSTRIDE + c * 8 + tig]);
                uint32_t a2 = __float_as_uint(B[gid * PSTRIDE + c * 8 + tig + 4]);
                uint32_t a3 = __float_as_uint(B[(gid + 8) * PSTRIDE + c * 8 + tig + 4]);
                mma_tf32(dac, a0, a1, a2, a3, vb0[c], vb1[c]);
            }
            // D column u lives on threads with tig == u>>1, component u&1
            if (tig == (u >> 1)) {
                int i0 = sidx[u * UPAD + sub * 16 + gid];
                int i1 = sidx[u * UPAD + sub * 16 + gid + 8];
                float p0 = (u & 1) ? dac[1] : dac[0];
                float p1 = (u & 1) ? dac[3] : dac[2];
                if (i0 != PAD_ID) acc += fmaf(C1, p0 * p0, -2.f * p0);
                if (i1 != PAD_ID) acc += fmaf(C1, p1 * p1, -2.f * p1);
            }
        };

        // 2-stage pipeline over groups warp, warp+8, ...
        stage(0, warp);
        int buf = 0;
        for (int g = warp; g < NGROUP; g += 8, buf ^= 1) {
            int gn = g + 8;
            if (gn < NGROUP) {
                stage(buf ^ 1, gn);
                asm volatile("cp.async.wait_group 1;\n" ::: "memory");
            } else {
                asm volatile("cp.async.wait_group 0;\n" ::: "memory");
            }
            __syncwarp();
            compute(buf, g);
        }

        // warp reduce (acc scattered over lanes) + block accumulate
        #pragma unroll
        for (int o = 16; o > 0; o >>= 1)
            acc += __shfl_xor_sync(0xffffffffu, acc, o);
        if (lane == 0) warpsum[warp] = acc;
        __syncthreads();
        if (tid == 0) {
            float s = 0.f;
            #pragma unroll
            for (int w = 0; w < 8; w++) s += warpsum[w];
            atomicAdd(&g_pos, s);
        }
    }

    // ================= last block combines + resets =================
    __threadfence();
    __syncthreads();
    if (tid == 0) s_rank = atomicAdd(&g_done, 1u);
    __syncthreads();

    if (s_rank == GRID_TOTAL - 1) {
        volatile float* v1 = g_g1;
        volatile float* v2 = g_gv;
        float s = 0.f;
        for (int e = tid; e < D * D; e += 256)
            s += v1[e] * v2[e];
        dynsm[tid] = s;
        __syncthreads();
        for (int off = 128; off > 0; off >>= 1) {
            if (tid < off) dynsm[tid] += dynsm[tid + off];
            __syncthreads();
        }
        if (tid == 0) {
            out[0] = NEGW * dynsm[0] + *(volatile float*)&g_pos;
            g_pos = 0.f;
            g_done = 0u;
        }
        for (int e = tid; e < D * D; e += 256) { g_g1[e] = 0.f; g_gv[e] = 0.f; }
    }
}

extern "C" void kernel_launch(void* const* d_in, const int* in_sizes, int n_in,
                              void* d_out, int out_size) {
    const int*   uids     = (const int*)d_in[0];
    const int*   pos_iids = (const int*)d_in[1];
    const float* userW    = (const float*)d_in[2];
    const float* itemW    = (const float*)d_in[3];
    const float* h        = (const float*)d_in[4];
    float* out = (float*)d_out;

    cudaFuncSetAttribute(enmf_kernel,
                         cudaFuncAttributeMaxDynamicSharedMemorySize, SMEM_DYN);
    enmf_kernel<<<GRID_TOTAL, 256, SMEM_DYN>>>(uids, pos_iids, userW, itemW, h, out);
}

// round 16
// speedup vs baseline: 2.9122x; 2.9122x over previous
#include <cuda_runtime.h>
#include <cstdint>

#define PAD_ID    100000
#define ITEM_ROWS 100001
#define D   64
#define NB  4096
#define L   200
#define NEGW 0.1f
#define C1  (1.0f - NEGW)

#define NB_G1   296
#define NB_GV   32
#define NB_GRAM (NB_G1 + NB_GV)   // 328
#define NB_POS  1024
#define B_PER_BLK 4
#define CHUNK   64
#define STRIDE  72
#define GRID_TOTAL (NB_GRAM + NB_POS)   // 1352

// ---- pos-path block-wide pipeline ----
#define UPAD    208                 // 13 groups of 16 rows per user
#define NGRP    52                  // 4 users * 13
#define NSTAGE  7                   // ceil(52/8) stages of 8 groups
#define SROWS   128                 // rows per stage (8 groups x 16)
#define PSTRIDE 68                  // floats per staged row -> conflict-free LDS
#define STAGE_F (SROWS * PSTRIDE)   // 8704 floats = 34816 B
#define RING    3
#define POS_F   (RING * STAGE_F)    // 26112 floats

#define SIDX_OFF   (POS_F * 4)                  // 104448 B
#define SIDX_BYTES (4 * UPAD * 4)               // 3328 B
#define VVEC_OFF   (SIDX_OFF + SIDX_BYTES)      // 107776 B
#define SMEM_DYN   (VVEC_OFF + B_PER_BLK * D * 4)   // 108800 B

__device__ float g_g1[D * D];
__device__ float g_gv[D * D];
__device__ float g_pos;
__device__ unsigned int g_done;

__device__ __forceinline__ float tf32r(float x) {
    uint32_t r;
    asm("cvt.rna.tf32.f32 %0, %1;" : "=r"(r) : "f"(x));
    return __uint_as_float(r);
}

__device__ __forceinline__ void mma_tf32(float d[4], uint32_t a0, uint32_t a1,
                                         uint32_t a2, uint32_t a3,
                                         uint32_t b0, uint32_t b1) {
    asm volatile(
        "mma.sync.aligned.m16n8k8.row.col.f32.tf32.tf32.f32 "
        "{%0,%1,%2,%3}, {%4,%5,%6,%7}, {%8,%9}, {%0,%1,%2,%3};\n"
        : "+f"(d[0]), "+f"(d[1]), "+f"(d[2]), "+f"(d[3])
        : "r"(a0), "r"(a1), "r"(a2), "r"(a3), "r"(b0), "r"(b1));
}

__device__ __forceinline__ void cp16(uint32_t dst_smem, const void* src) {
    asm volatile("cp.async.cg.shared.global [%0], [%1], 16;\n"
                 :: "r"(dst_smem), "l"(src));
}

__global__ __launch_bounds__(256) void enmf_kernel(
    const int* __restrict__ uids, const int* __restrict__ pos_iids,
    const float* __restrict__ userW, const float* __restrict__ itemW,
    const float* __restrict__ h, float* __restrict__ out)
{
    extern __shared__ float dynsm[];
    __shared__ float hh[D];
    __shared__ float warpsum[8];
    __shared__ unsigned int s_rank;

    const int tid = threadIdx.x;
    const int bid = blockIdx.x;
    if (tid < D) hh[tid] = h[tid];
    __syncthreads();

    int gram_id = -1, pos_id = -1;
    if (bid < NB_GRAM * 4) {
        if ((bid & 3) == 3) gram_id = bid >> 2;
        else                pos_id  = (bid >> 2) * 3 + (bid & 3);
    } else {
        pos_id = NB_GRAM * 3 + (bid - NB_GRAM * 4);
    }

    const int warp = tid >> 5, lane = tid & 31;
    const int gid  = lane >> 2;       // 0..7
    const int tig  = lane & 3;        // 0..3

    if (gram_id >= 0) {
        // ========= Gram path: tf32 mma, double-buffered fill (unchanged) =========
        const bool is_item   = (gram_id < NB_G1);
        const int rows_total = is_item ? ITEM_ROWS : NB;
        const int nblk       = is_item ? NB_G1 : NB_GV;
        const int gb         = is_item ? gram_id : gram_id - NB_G1;
        const int per        = (rows_total + nblk - 1) / nblk;
        const int r0         = gb * per;
        const int r1         = min(r0 + per, rows_total);

        const bool compute_warp = (warp < 4);
        const int Ibase = warp * 16;

        float dacc[8][4];
        #pragma unroll
        for (int n = 0; n < 8; n++)
            #pragma unroll
            for (int k = 0; k < 4; k++) dacc[n][k] = 0.f;

        const float4* hv4 = (const float4*)hh;
        float* smA = dynsm;

        auto fill = [&](int buf, int base, int lo) {
            for (int i = tid - lo; i < CHUNK * 16; i += 256 - lo) {
                if (i < 0) continue;
                int r = base + (i >> 4);
                int c4 = i & 15;
                float4 v = make_float4(0.f, 0.f, 0.f, 0.f);
                if (r < r1) {
                    if (is_item) {
                        v = ((const float4*)itemW)[(size_t)r * 16 + c4];
                    } else {
                        float4 u = ((const float4*)userW)[(size_t)uids[r] * 16 + c4];
                        float4 hx = hv4[c4];
                        v = make_float4(u.x * hx.x, u.y * hx.y, u.z * hx.z, u.w * hx.w);
                    }
                    v.x = tf32r(v.x); v.y = tf32r(v.y);
                    v.z = tf32r(v.z); v.w = tf32r(v.w);
                }
                ((float4*)(smA + buf * (CHUNK * STRIDE) + (i >> 4) * STRIDE))[c4] = v;
            }
        };

        fill(0, r0, 0);
        __syncthreads();

        int buf = 0;
        for (int base = r0; base < r1; base += CHUNK, buf ^= 1) {
            if (!compute_warp) {
                if (base + CHUNK < r1) fill(buf ^ 1, base + CHUNK, 128);
            } else {
                #pragma unroll
                for (int ks = 0; ks < 8; ks++) {
                    const float* r0p = smA + buf * (CHUNK * STRIDE) + (ks * 8 + tig) * STRIDE;
                    const float* r1p = smA + buf * (CHUNK * STRIDE) + (ks * 8 + tig + 4) * STRIDE;
                    uint32_t a0 = __float_as_uint(r0p[Ibase + gid]);
                    uint32_t a1 = __float_as_uint(r0p[Ibase + gid + 8]);
                    uint32_t a2 = __float_as_uint(r1p[Ibase + gid]);
                    uint32_t a3 = __float_as_uint(r1p[Ibase + gid + 8]);
                    #pragma unroll
                    for (int nt = 0; nt < 8; nt++) {
                        uint32_t b0 = __float_as_uint(r0p[nt * 8 + gid]);
                        uint32_t b1 = __float_as_uint(r1p[nt * 8 + gid]);
                        mma_tf32(dacc[nt], a0, a1, a2, a3, b0, b1);
                    }
                }
            }
            __syncthreads();
        }

        if (compute_warp) {
            float* dst = is_item ? g_g1 : g_gv;
            const int row0 = Ibase + gid;
            #pragma unroll
            for (int nt = 0; nt < 8; nt++) {
                int col = nt * 8 + tig * 2;
                atomicAdd(&dst[row0 * D + col],           dacc[nt][0]);
                atomicAdd(&dst[row0 * D + col + 1],       dacc[nt][1]);
                atomicAdd(&dst[(row0 + 8) * D + col],     dacc[nt][2]);
                atomicAdd(&dst[(row0 + 8) * D + col + 1], dacc[nt][3]);
            }
        }
    } else {
        // ===== pos path: block-wide 3-slot cp.async ring + tf32 mma dots =====
        const int b0 = pos_id * B_PER_BLK;
        int*   sidx = (int*)((char*)dynsm + SIDX_OFF);
        float* vvec = (float*)((char*)dynsm + VVEC_OFF);

        for (int i = tid; i < B_PER_BLK * D; i += 256) {
            int bl = i >> 6, d = i & 63;
            vvec[i] = userW[(size_t)uids[b0 + bl] * D + d] * hh[d];
        }
        for (int j = tid; j < 4 * UPAD; j += 256) {
            int u = j / UPAD;
            int p = j - u * UPAD;
            sidx[j] = (p < L) ? pos_iids[(size_t)(b0 + u) * L + p] : PAD_ID;
        }
        __syncthreads();

        // B fragments: column n=gid holds user gid's v (gid>=4 -> zero). Validated R15.
        uint32_t vb0[8], vb1[8];
        #pragma unroll
        for (int c = 0; c < 8; c++) {
            float x0 = (gid < 4) ? tf32r(vvec[gid * D + c * 8 + tig])     : 0.f;
            float x1 = (gid < 4) ? tf32r(vvec[gid * D + c * 8 + tig + 4]) : 0.f;
            vb0[c] = __float_as_uint(x0);
            vb1[c] = __float_as_uint(x1);
        }

        uint32_t smem_u32 = (uint32_t)__cvta_generic_to_shared(dynsm);
        float acc = 0.f;

        // stage s: groups s*8..s*8+7; group g -> user g&3, group-idx g>>2, 16 rows
        auto stage_fn = [&](int s) {
            uint32_t sb = smem_u32 + (uint32_t)(s % RING) * (STAGE_F * 4);
            #pragma unroll
            for (int i = tid; i < SROWS * 16; i += 256) {
                int row = i >> 4, seg = i & 15;
                int g = s * 8 + (row >> 4);
                if (g < NGRP) {
                    int u = g & 3, j = g >> 2, r = row & 15;
                    int idx = sidx[u * UPAD + j * 16 + r];
                    cp16(sb + (uint32_t)(row * PSTRIDE + seg * 4) * 4,
                         (const char*)(itemW + (size_t)idx * D) + seg * 16);
                }
            }
            asm volatile("cp.async.commit_group;\n" ::: "memory");
        };

        stage_fn(0);
        stage_fn(1);
        for (int k = 0; k < NSTAGE; k++) {
            if (k < NSTAGE - 1)
                asm volatile("cp.async.wait_group 1;\n" ::: "memory");
            else
                asm volatile("cp.async.wait_group 0;\n" ::: "memory");
            __syncthreads();                 // all threads see stage k complete
            if (k + 2 < NSTAGE) stage_fn(k + 2);   // slot (k+2)%3: disjoint from k%3, (k+1)%3

            int g = k * 8 + warp;
            if (g < NGRP) {
                int u = g & 3, j = g >> 2;
                const float* A = dynsm + (k % RING) * STAGE_F + warp * 16 * PSTRIDE;
                float dac[4] = {0.f, 0.f, 0.f, 0.f};
                #pragma unroll
                for (int c = 0; c < 8; c++) {
                    uint32_t a0 = __float_as_uint(A[gid * PSTRIDE + c * 8 + tig]);
                    uint32_t a1 = __float_as_uint(A[(gid + 8) * PSTRIDE + c * 8 + tig]);
                    uint32_t a2 = __float_as_uint(A[gid * PSTRIDE + c * 8 + tig + 4]);
                    uint32_t a3 = __float_as_uint(A[(gid + 8) * PSTRIDE + c * 8 + tig + 4]);
                    mma_tf32(dac, a0, a1, a2, a3, vb0[c], vb1[c]);
                }
                // D column u: threads tig == u>>1, component u&1 (validated R15)
                if (tig == (u >> 1)) {
                    int i0 = sidx[u * UPAD + j * 16 + gid];
                    int i1 = sidx[u * UPAD + j * 16 + gid + 8];
                    float p0 = (u & 1) ? dac[1] : dac[0];
                    float p1 = (u & 1) ? dac[3] : dac[2];
                    if (i0 != PAD_ID) acc += fmaf(C1, p0 * p0, -2.f * p0);
                    if (i1 != PAD_ID) acc += fmaf(C1, p1 * p1, -2.f * p1);
                }
            }
        }

        #pragma unroll
        for (int o = 16; o > 0; o >>= 1)
            acc += __shfl_xor_sync(0xffffffffu, acc, o);
        if (lane == 0) warpsum[warp] = acc;
        __syncthreads();
        if (tid == 0) {
            float s = 0.f;
            #pragma unroll
            for (int w = 0; w < 8; w++) s += warpsum[w];
            atomicAdd(&g_pos, s);
        }
    }

    // ================= last block combines + resets =================
    __threadfence();
    __syncthreads();
    if (tid == 0) s_rank = atomicAdd(&g_done, 1u);
    __syncthreads();

    if (s_rank == GRID_TOTAL - 1) {
        volatile float* v1 = g_g1;
        volatile float* v2 = g_gv;
        float s = 0.f;
        for (int e = tid; e < D * D; e += 256)
            s += v1[e] * v2[e];
        dynsm[tid] = s;
        __syncthreads();
        for (int off = 128; off > 0; off >>= 1) {
            if (tid < off) dynsm[tid] += dynsm[tid + off];
            __syncthreads();
        }
        if (tid == 0) {
            out[0] = NEGW * dynsm[0] + *(volatile float*)&g_pos;
            g_pos = 0.f;
            g_done = 0u;
        }
        for (int e = tid; e < D * D; e += 256) { g_g1[e] = 0.f; g_gv[e] = 0.f; }
    }
}

extern "C" void kernel_launch(void* const* d_in, const int* in_sizes, int n_in,
                              void* d_out, int out_size) {
    const int*   uids     = (const int*)d_in[0];
    const int*   pos_iids = (const int*)d_in[1];
    const float* userW    = (const float*)d_in[2];
    const float* itemW    = (const float*)d_in[3];
    const float* h        = (const float*)d_in[4];
    float* out = (float*)d_out;

    cudaFuncSetAttribute(enmf_kernel,
                         cudaFuncAttributeMaxDynamicSharedMemorySize, SMEM_DYN);
    enmf_kernel<<<GRID_TOTAL, 256, SMEM_DYN>>>(uids, pos_iids, userW, itemW, h, out);
}